// round 16
// baseline (speedup 1.0000x reference)
#include <cuda_runtime.h>
#include <cuda_bf16.h>
#include <cstdint>

// ---------------------------------------------------------------------------
// Attention_26379689132660 — fused kernel: cp.async z-tile in smem, 2px/thread
// f32x2 math, ~28 warps/SM.
//
// Algebraic collapse: the network is affine in the 3-channel z_t, folding to
// per-head 3x3 forms:
//   score_h(t) = vq_h . z_t,  vq_h = u_h + z7^T M_h   (SC*log2e folded in;
//     t-constant terms dropped: softmax-invariant; scores bounded -> no max)
//   out = pC + sum_h G_h zbar_h,  zbar_h = softmax-mean of z_t
//
// R13 lesson: one-wave kernel -> warps/SM = total_warps/148; binding
// constraint was 14 warps/SM + z-LDGs queued ahead of the fold's weight loads
// (per-SM L1tex FIFO). Fixes:
//  * 1024 blocks x 128 thr (2px/thread) = 28 warps/SM; z tile lives in smem
//    via cp.async (no registers, no FIFO hazard), compute re-reads it t-by-t
//    through forced ld.shared so ptxas can't re-inflate register pressure.
//  * fold overlaps the z DMA; weight rows loaded 1 thread = 1 cache line.
// R15: fix missing <cstdint> (uint32_t) — design unchanged.
// ---------------------------------------------------------------------------

typedef unsigned long long u64;
typedef unsigned int u32;

__device__ __forceinline__ u64 pk2(float x, float y) {
    u64 r; asm("mov.b64 %0,{%1,%2};" : "=l"(r) : "f"(x), "f"(y)); return r;
}
__device__ __forceinline__ void up2(u64 v, float& x, float& y) {
    asm("mov.b64 {%0,%1},%2;" : "=f"(x), "=f"(y) : "l"(v));
}
__device__ __forceinline__ u64 f2fma(u64 a, u64 b, u64 c) {
    u64 d; asm("fma.rn.f32x2 %0,%1,%2,%3;" : "=l"(d) : "l"(a), "l"(b), "l"(c)); return d;
}
__device__ __forceinline__ u64 f2mul(u64 a, u64 b) {
    u64 d; asm("mul.rn.f32x2 %0,%1,%2;" : "=l"(d) : "l"(a), "l"(b)); return d;
}
__device__ __forceinline__ u64 f2add(u64 a, u64 b) {
    u64 d; asm("add.rn.f32x2 %0,%1,%2;" : "=l"(d) : "l"(a), "l"(b)); return d;
}
__device__ __forceinline__ float ex2a(float x) {
    float y; asm("ex2.approx.ftz.f32 %0,%1;" : "=f"(y) : "f"(x)); return y;
}
__device__ __forceinline__ float rcpa(float x) {
    float y; asm("rcp.approx.ftz.f32 %0,%1;" : "=f"(y) : "f"(x)); return y;
}
// Forced shared read: volatile so ptxas cannot CSE z reads across heads
// (which would re-inflate register pressure to R13 levels).
__device__ __forceinline__ u64 lds64(u32 a) {
    u64 v; asm volatile("ld.shared.b64 %0,[%1];" : "=l"(v) : "r"(a)); return v;
}

// SC = (1/sqrt(8)) * log2(e), folded into M and u.
#define SC_FOLD (0.3535533905932738f * 1.4426950408889634f)

__global__ __launch_bounds__(128, 7) void attn_fused_kernel(
    const float4* __restrict__ Z16,  // (4,8,3,256,256) as 16B units
    u64* __restrict__ O2,            // (4,3,256,256) as pixel-pairs
    const float* __restrict__ W_in, const float* __restrict__ b_in,
    const float* __restrict__ W_q,  const float* __restrict__ b_q,
    const float* __restrict__ W_k,
    const float* __restrict__ W_v,  const float* __restrict__ b_v,
    const float* __restrict__ W_o,  const float* __restrict__ b_o)
{
    __shared__ u64  zsh[24 * 128];         // 24 KB: [channel][pair-in-block]
    __shared__ float sWin[96], sWo[96];
    __shared__ float sbin[32], sbq[32], sbv[32];
    __shared__ float sA[288];              // A_q | A_k | A_v, [X*96 + d*3 + c]
    __shared__ float sCq[32], sCv[32];
    __shared__ u64  pM[36], pU[12], pG[36], pC[3];   // lane-duplicated

    const int tid     = threadIdx.x;
    const int b       = blockIdx.x >> 8;          // 256 blocks per batch
    const int g0      = (blockIdx.x & 255) * 128; // pair offset in plane
    const int plane2  = 32768;                    // u64 pairs per plane
    const int plane16 = 16384;                    // 16B units per plane

    const u32 zbase = (u32)__cvta_generic_to_shared(zsh);

    // ---- Stage A: cp.async the 24 KB z tile (12 x 16B per thread).
    // Issued first: DRAM burst starts immediately, no registers consumed,
    // and the fold's weight LDGs below are not stuck behind it on scoreboard.
    {
        const float4* src = Z16 + (size_t)b * 24 * plane16 + (g0 >> 1);
        #pragma unroll
        for (int k = 0; k < 12; k++) {
            int u   = k * 128 + tid;       // 0..1535 16B-units
            int ch  = u >> 6;              // 0..23
            int pos = u & 63;
            u32 dst = zbase + ch * 1024 + pos * 16;
            const float4* s = src + ch * plane16 + pos;
            asm volatile("cp.async.cg.shared.global [%0], [%1], 16;"
                         :: "r"(dst), "l"(s));
        }
        asm volatile("cp.async.commit_group;");
    }

    // ---- Stage B: stage small params (coalesced).
    if (tid < 96) { sWin[tid] = __ldg(W_in + tid); sWo[tid] = __ldg(W_o + tid); }
    if (tid < 32)       sbin[tid]      = __ldg(b_in + tid);
    else if (tid < 64)  sbq[tid - 32]  = __ldg(b_q + (tid - 32));
    else if (tid < 96)  sbv[tid - 64]  = __ldg(b_v + (tid - 64));

    // ---- Stage C: each of 96 threads owns one 32-float weight row
    // (= exactly one 128B line; no strided-warp pathology, no sW staging).
    float r[32];
    const int X = tid >> 5, d = tid & 31;
    if (tid < 96) {
        const float4* Wp =
            ((X == 0) ? (const float4*)W_q :
             (X == 1) ? (const float4*)W_k : (const float4*)W_v) + d * 8;
        #pragma unroll
        for (int i = 0; i < 8; i++) {
            float4 w = __ldg(Wp + i);
            r[4*i] = w.x; r[4*i+1] = w.y; r[4*i+2] = w.z; r[4*i+3] = w.w;
        }
    }
    __syncthreads();   // sWin/sbin/sbq/sbv ready

    // ---- Stage D: A_X[d][c] = row . Win[:,c];  c_q/c_v = row . b_in + b_X
    if (tid < 96) {
        float a0 = 0.f, a1 = 0.f, a2 = 0.f;
        #pragma unroll
        for (int i = 0; i < 32; i++) {
            a0 += r[i] * sWin[i * 3 + 0];
            a1 += r[i] * sWin[i * 3 + 1];
            a2 += r[i] * sWin[i * 3 + 2];
        }
        sA[X * 96 + d * 3 + 0] = a0;
        sA[X * 96 + d * 3 + 1] = a1;
        sA[X * 96 + d * 3 + 2] = a2;
        if (X != 1) {
            float cc = (X == 0) ? sbq[d] : sbv[d];
            #pragma unroll
            for (int i = 0; i < 32; i++) cc += r[i] * sbin[i];
            if (X == 0) sCq[d] = cc; else sCv[d] = cc;
        }
    }
    __syncthreads();

    // ---- Stage E: 87 derived scalars, lane-duplicated u64.
    if (tid < 36) {                        // M[h][a][c] (fold SC)
        int h = tid / 9, a = (tid / 3) % 3, c = tid % 3;
        float s = 0.f;
        #pragma unroll
        for (int j = 0; j < 8; j++)
            s += sA[(h * 8 + j) * 3 + a] * sA[96 + (h * 8 + j) * 3 + c];
        s *= SC_FOLD;
        pM[h * 9 + a * 3 + c] = pk2(s, s);
    } else if (tid < 48) {                 // u[h][c] (fold SC)
        int t2 = tid - 36, h = t2 / 3, c = t2 % 3;
        float s = 0.f;
        #pragma unroll
        for (int j = 0; j < 8; j++)
            s += sCq[h * 8 + j] * sA[96 + (h * 8 + j) * 3 + c];
        s *= SC_FOLD;
        pU[h * 3 + c] = pk2(s, s);
    } else if (tid < 84) {                 // G[h][o][c]
        int t2 = tid - 48, h = t2 / 9, o = (t2 / 3) % 3, c = t2 % 3;
        float s = 0.f;
        #pragma unroll
        for (int j = 0; j < 8; j++)
            s += sWo[o * 32 + h * 8 + j] * sA[192 + (h * 8 + j) * 3 + c];
        pG[h * 9 + o * 3 + c] = pk2(s, s);
    } else if (tid < 87) {                 // pC[o] = b_o + W_o . c_v
        int o = tid - 84;
        float s = __ldg(b_o + o);
        #pragma unroll
        for (int dd = 0; dd < 32; dd++) s += sWo[o * 32 + dd] * sCv[dd];
        pC[o] = pk2(s, s);
    }

    asm volatile("cp.async.wait_group 0;");
    __syncthreads();   // z tile + derived params visible

    // ---- Stage F: attention math, 2 px/thread in f32x2 lanes.
    // z re-read t-by-t from smem (lds64 is volatile: regs stay low).
    const u32 za0 = zbase + tid * 8;       // this thread's pair, channel 0
    const u64 z70 = lds64(za0 + 21 * 1024);
    const u64 z71 = lds64(za0 + 22 * 1024);
    const u64 z72 = lds64(za0 + 23 * 1024);

    u64 o0 = pC[0], o1 = pC[1], o2 = pC[2];

    #pragma unroll
    for (int hd = 0; hd < 4; hd++) {
        const u64* M = pM + hd * 9;
        const u64* U = pU + hd * 3;
        const u64* G = pG + hd * 9;

        u64 vq0 = f2fma(z70, M[0], U[0]);
        vq0     = f2fma(z71, M[3], vq0);
        vq0     = f2fma(z72, M[6], vq0);
        u64 vq1 = f2fma(z70, M[1], U[1]);
        vq1     = f2fma(z71, M[4], vq1);
        vq1     = f2fma(z72, M[7], vq1);
        u64 vq2 = f2fma(z70, M[2], U[2]);
        vq2     = f2fma(z71, M[5], vq2);
        vq2     = f2fma(z72, M[8], vq2);

        u64 esum = 0, zb0 = 0, zb1 = 0, zb2 = 0;
        #pragma unroll
        for (int t = 0; t < 8; t++) {
            u64 za = lds64(za0 + (t * 3 + 0) * 1024);
            u64 zb = lds64(za0 + (t * 3 + 1) * 1024);
            u64 zc = lds64(za0 + (t * 3 + 2) * 1024);
            u64 s = f2mul(vq0, za);
            s = f2fma(vq1, zb, s);
            s = f2fma(vq2, zc, s);
            float x, y; up2(s, x, y);
            u64 e = pk2(ex2a(x), ex2a(y));
            esum = f2add(esum, e);
            zb0 = f2fma(e, za, zb0);
            zb1 = f2fma(e, zb, zb1);
            zb2 = f2fma(e, zc, zb2);
        }
        float e0, e1; up2(esum, e0, e1);
        u64 pinv = pk2(rcpa(e0), rcpa(e1));
        zb0 = f2mul(zb0, pinv); zb1 = f2mul(zb1, pinv); zb2 = f2mul(zb2, pinv);

        o0 = f2fma(G[0], zb0, o0);
        o0 = f2fma(G[1], zb1, o0);
        o0 = f2fma(G[2], zb2, o0);
        o1 = f2fma(G[3], zb0, o1);
        o1 = f2fma(G[4], zb1, o1);
        o1 = f2fma(G[5], zb2, o1);
        o2 = f2fma(G[6], zb0, o2);
        o2 = f2fma(G[7], zb1, o2);
        o2 = f2fma(G[8], zb2, o2);
    }

    // ---- Stage G: coalesced STG.64 (pixel pair per store), 3 planes.
    u64* op = O2 + (size_t)b * 3 * plane2 + g0 + tid;
    op[0]          = o0;
    op[plane2]     = o1;
    op[2 * plane2] = o2;
}

extern "C" void kernel_launch(void* const* d_in, const int* in_sizes, int n_in,
                              void* d_out, int out_size)
{
    const float* Z    = (const float*)d_in[0];
    const float* W_in = (const float*)d_in[1];
    const float* b_in = (const float*)d_in[2];
    const float* W_q  = (const float*)d_in[3];
    const float* b_q  = (const float*)d_in[4];
    const float* W_k  = (const float*)d_in[5];
    // b_k (d_in[6]) provably unused: its score contribution is constant over t
    const float* W_v  = (const float*)d_in[7];
    const float* b_v  = (const float*)d_in[8];
    const float* W_o  = (const float*)d_in[9];
    const float* b_o  = (const float*)d_in[10];

    // 262144 pixels / 2 per thread / 128 threads = 1024 blocks, one kernel.
    attn_fused_kernel<<<1024, 128>>>(
        (const float4*)Z, (u64*)d_out,
        W_in, b_in, W_q, b_q, W_k, W_v, b_v, W_o, b_o);
}

// round 17
// speedup vs baseline: 1.6275x; 1.6275x over previous
#include <cuda_runtime.h>
#include <cuda_bf16.h>
#include <cstdint>

// ---------------------------------------------------------------------------
// Attention_26379689132660 — fused kernel, weights-first FIFO ordering.
//
// Algebraic collapse: the network is affine in the 3-channel z_t, folding to
// per-head 3x3 forms:
//   score_h(t) = vq_h . z_t,  vq_h = u_h + z7^T M_h   (SC*log2e folded in;
//     t-constant terms dropped: softmax-invariant; scores bounded -> no max)
//   out = pC + sum_h G_h zbar_h,  zbar_h = softmax-mean of z_t
//
// R16 lesson: occupancy is NOT the lever (38% occ ran 75% slower on LDS
// rereads); per-warp critical path is. R13 geometry (512x128, 4 px/thread,
// z in regs via LDG.128, f32x2 math) kept. Fix R13's serial prefix:
//  * L1tex completes in SASS-issue order (per-SM FIFO) — so weights now go
//    FIRST via cp.async (no regs, no stall), z-LDG.128 burst second. The fold
//    overlaps the z stream instead of waiting behind it.
//  * b_o prefetched before the burst (was a cold LDG inside stage E).
//  * stage D reads weight rows from smem with rotated index -> conflict-free.
// ---------------------------------------------------------------------------

typedef unsigned long long u64;
typedef unsigned int u32;

__device__ __forceinline__ u64 pk2(float x, float y) {
    u64 r; asm("mov.b64 %0,{%1,%2};" : "=l"(r) : "f"(x), "f"(y)); return r;
}
__device__ __forceinline__ void up2(u64 v, float& x, float& y) {
    asm("mov.b64 {%0,%1},%2;" : "=f"(x), "=f"(y) : "l"(v));
}
__device__ __forceinline__ u64 f2fma(u64 a, u64 b, u64 c) {
    u64 d; asm("fma.rn.f32x2 %0,%1,%2,%3;" : "=l"(d) : "l"(a), "l"(b), "l"(c)); return d;
}
__device__ __forceinline__ u64 f2mul(u64 a, u64 b) {
    u64 d; asm("mul.rn.f32x2 %0,%1,%2;" : "=l"(d) : "l"(a), "l"(b)); return d;
}
__device__ __forceinline__ u64 f2add(u64 a, u64 b) {
    u64 d; asm("add.rn.f32x2 %0,%1,%2;" : "=l"(d) : "l"(a), "l"(b)); return d;
}
__device__ __forceinline__ float ex2a(float x) {
    float y; asm("ex2.approx.ftz.f32 %0,%1;" : "=f"(y) : "f"(x)); return y;
}
__device__ __forceinline__ float rcpa(float x) {
    float y; asm("rcp.approx.ftz.f32 %0,%1;" : "=f"(y) : "f"(x)); return y;
}

// SC = (1/sqrt(8)) * log2(e), folded into M and u.
#define SC_FOLD (0.3535533905932738f * 1.4426950408889634f)

__global__ __launch_bounds__(128, 3) void attn_fused_kernel(
    const ulonglong2* __restrict__ Z4,   // (4,8,3,256,256): 4 px per 16B
    ulonglong2* __restrict__ O4,         // (4,3,256,256):   4 px per 16B
    const float* __restrict__ W_in, const float* __restrict__ b_in,
    const float* __restrict__ W_q,  const float* __restrict__ b_q,
    const float* __restrict__ W_k,
    const float* __restrict__ W_v,  const float* __restrict__ b_v,
    const float* __restrict__ W_o,  const float* __restrict__ b_o)
{
    __shared__ __align__(16) float sW[3 * 1024];  // 12KB: Wq|Wk|Wv
    __shared__ __align__(16) float sS[288];       // Win|Wo|bin|bq|bv
    __shared__ float sbo[3];
    __shared__ float sA[288];                     // A_q|A_k|A_v, [X*96+d*3+c]
    __shared__ float sCq[32], sCv[32];
    __shared__ u64 pM[36], pU[12], pG[36], pC[3]; // lane-duplicated

    const int tid    = threadIdx.x;
    const int plane4 = 16384;                     // 16B units per plane
    const int b      = blockIdx.x >> 7;           // 128 blocks per batch
    const int g0     = (blockIdx.x & 127) * 128;

    // ---- Stage A: b_o prefetch (3 regs), then ALL weights via cp.async —
    // these enter the L1tex FIFO FIRST, so the fold is never stuck behind
    // the z burst.
    float wbo = (tid < 3) ? __ldg(b_o + tid) : 0.f;

    {
        u32 sSb = (u32)__cvta_generic_to_shared(sS);
        if (tid < 72) {                           // 288 floats = 72 x 16B
            const float* src;
            if      (tid < 24) src = W_in + tid * 4;
            else if (tid < 48) src = W_o  + (tid - 24) * 4;
            else if (tid < 56) src = b_in + (tid - 48) * 4;
            else if (tid < 64) src = b_q  + (tid - 56) * 4;
            else               src = b_v  + (tid - 64) * 4;
            asm volatile("cp.async.cg.shared.global [%0], [%1], 16;"
                         :: "r"(sSb + tid * 16), "l"(src));
        }
        u32 sWb = (u32)__cvta_generic_to_shared(sW);
        #pragma unroll
        for (int k = 0; k < 6; k++) {             // 3072 floats = 768 x 16B
            int u = k * 128 + tid;                // 0..767
            int X = u >> 8;
            const float* src = ((X == 0) ? W_q : (X == 1) ? W_k : W_v)
                               + (u & 255) * 4;
            asm volatile("cp.async.cg.shared.global [%0], [%1], 16;"
                         :: "r"(sWb + u * 16), "l"(src));
        }
        asm volatile("cp.async.commit_group;");
    }

    // ---- Stage B: the z burst — 24 LDG.128 into registers (R13-proven).
    // z[0] = pixel pair (0,1), z[1] = pixel pair (2,3), lanes packed f32x2.
    u64 z[2][8][3];
    {
        const ulonglong2* p = Z4 + (size_t)b * 24 * plane4 + g0 + tid;
        #pragma unroll
        for (int t = 0; t < 8; t++)
            #pragma unroll
            for (int c = 0; c < 3; c++) {
                ulonglong2 v = __ldg(p + (t * 3 + c) * plane4);
                z[0][t][c] = v.x;
                z[1][t][c] = v.y;
            }
    }

    if (tid < 3) sbo[tid] = wbo;   // b_o returned long ago (first in FIFO)

    asm volatile("cp.async.wait_group 0;");
    __syncthreads();               // weights + sbo visible

    const float* sWin = sS;        // 96
    const float* sWo  = sS + 96;   // 96
    const float* sbin = sS + 192;  // 32
    const float* sbq  = sS + 224;  // 32
    const float* sbv  = sS + 256;  // 32

    // ---- Stage C: A_X[d] = row_d(W_X) @ W_in ; c_q/c_v = row . b_in + b_X.
    // Rotated index (d+j)&31 -> conflict-free smem banks without padding.
    {
        const int X = tid >> 5, d = tid & 31;
        if (tid < 96) {
            float a0 = 0.f, a1 = 0.f, a2 = 0.f, cacc = 0.f;
            #pragma unroll
            for (int j = 0; j < 32; j++) {
                int i = (d + j) & 31;
                float w = sW[X * 1024 + d * 32 + i];
                a0   += w * sWin[i * 3 + 0];
                a1   += w * sWin[i * 3 + 1];
                a2   += w * sWin[i * 3 + 2];
                cacc += w * sbin[i];
            }
            sA[X * 96 + d * 3 + 0] = a0;
            sA[X * 96 + d * 3 + 1] = a1;
            sA[X * 96 + d * 3 + 2] = a2;
            if (X == 0)      sCq[d] = sbq[d] + cacc;
            else if (X == 2) sCv[d] = sbv[d] + cacc;
        }
    }
    __syncthreads();

    // ---- Stage D: 87 derived scalars, lane-duplicated u64.
    if (tid < 36) {                        // M[h][a][c] (fold SC)
        int h = tid / 9, a = (tid / 3) % 3, c = tid % 3;
        float s = 0.f;
        #pragma unroll
        for (int j = 0; j < 8; j++)
            s += sA[(h * 8 + j) * 3 + a] * sA[96 + (h * 8 + j) * 3 + c];
        s *= SC_FOLD;
        pM[h * 9 + a * 3 + c] = pk2(s, s);
    } else if (tid < 48) {                 // u[h][c] (fold SC)
        int t2 = tid - 36, h = t2 / 3, c = t2 % 3;
        float s = 0.f;
        #pragma unroll
        for (int j = 0; j < 8; j++)
            s += sCq[h * 8 + j] * sA[96 + (h * 8 + j) * 3 + c];
        s *= SC_FOLD;
        pU[h * 3 + c] = pk2(s, s);
    } else if (tid < 84) {                 // G[h][o][c]
        int t2 = tid - 48, h = t2 / 9, o = (t2 / 3) % 3, c = t2 % 3;
        float s = 0.f;
        #pragma unroll
        for (int j = 0; j < 8; j++)
            s += sWo[o * 32 + h * 8 + j] * sA[192 + (h * 8 + j) * 3 + c];
        pG[h * 9 + o * 3 + c] = pk2(s, s);
    } else if (tid < 87) {                 // pC[o] = b_o + W_o . c_v
        int o = tid - 84;
        float s = sbo[o];
        #pragma unroll
        for (int dd = 0; dd < 32; dd++) s += sWo[o * 32 + dd] * sCv[dd];
        pC[o] = pk2(s, s);
    }
    __syncthreads();

    // ---- Stage E: attention math — two independent f32x2 chains (pixel
    // pairs). One-pass softmax. (R13-proven compute body.)
    u64 o[2][3];
    o[0][0] = pC[0]; o[0][1] = pC[1]; o[0][2] = pC[2];
    o[1][0] = pC[0]; o[1][1] = pC[1]; o[1][2] = pC[2];

    #pragma unroll
    for (int hd = 0; hd < 4; hd++) {
        const u64* M = pM + hd * 9;
        const u64* U = pU + hd * 3;
        const u64* G = pG + hd * 9;
        #pragma unroll
        for (int p = 0; p < 2; p++) {
            u64 vq0 = f2fma(z[p][7][0], M[0], U[0]);
            vq0     = f2fma(z[p][7][1], M[3], vq0);
            vq0     = f2fma(z[p][7][2], M[6], vq0);
            u64 vq1 = f2fma(z[p][7][0], M[1], U[1]);
            vq1     = f2fma(z[p][7][1], M[4], vq1);
            vq1     = f2fma(z[p][7][2], M[7], vq1);
            u64 vq2 = f2fma(z[p][7][0], M[2], U[2]);
            vq2     = f2fma(z[p][7][1], M[5], vq2);
            vq2     = f2fma(z[p][7][2], M[8], vq2);

            u64 esum = 0, zb0 = 0, zb1 = 0, zb2 = 0;
            #pragma unroll
            for (int t = 0; t < 8; t++) {
                u64 s = f2mul(vq0, z[p][t][0]);
                s = f2fma(vq1, z[p][t][1], s);
                s = f2fma(vq2, z[p][t][2], s);
                float x, y; up2(s, x, y);
                u64 e = pk2(ex2a(x), ex2a(y));
                esum = f2add(esum, e);
                zb0 = f2fma(e, z[p][t][0], zb0);
                zb1 = f2fma(e, z[p][t][1], zb1);
                zb2 = f2fma(e, z[p][t][2], zb2);
            }
            float e0, e1; up2(esum, e0, e1);
            u64 pinv = pk2(rcpa(e0), rcpa(e1));
            zb0 = f2mul(zb0, pinv); zb1 = f2mul(zb1, pinv); zb2 = f2mul(zb2, pinv);

            o[p][0] = f2fma(G[0], zb0, o[p][0]);
            o[p][0] = f2fma(G[1], zb1, o[p][0]);
            o[p][0] = f2fma(G[2], zb2, o[p][0]);
            o[p][1] = f2fma(G[3], zb0, o[p][1]);
            o[p][1] = f2fma(G[4], zb1, o[p][1]);
            o[p][1] = f2fma(G[5], zb2, o[p][1]);
            o[p][2] = f2fma(G[6], zb0, o[p][2]);
            o[p][2] = f2fma(G[7], zb1, o[p][2]);
            o[p][2] = f2fma(G[8], zb2, o[p][2]);
        }
    }

    // ---- Stage F: coalesced STG.128 (4 px per store), 3 planes.
    ulonglong2* op = O4 + (size_t)b * 3 * plane4 + g0 + tid;
    ulonglong2 r0; r0.x = o[0][0]; r0.y = o[1][0];
    ulonglong2 r1; r1.x = o[0][1]; r1.y = o[1][1];
    ulonglong2 r2; r2.x = o[0][2]; r2.y = o[1][2];
    op[0]          = r0;
    op[plane4]     = r1;
    op[2 * plane4] = r2;
}

extern "C" void kernel_launch(void* const* d_in, const int* in_sizes, int n_in,
                              void* d_out, int out_size)
{
    const float* Z    = (const float*)d_in[0];
    const float* W_in = (const float*)d_in[1];
    const float* b_in = (const float*)d_in[2];
    const float* W_q  = (const float*)d_in[3];
    const float* b_q  = (const float*)d_in[4];
    const float* W_k  = (const float*)d_in[5];
    // b_k (d_in[6]) provably unused: its score contribution is constant over t
    const float* W_v  = (const float*)d_in[7];
    const float* b_v  = (const float*)d_in[8];
    const float* W_o  = (const float*)d_in[9];
    const float* b_o  = (const float*)d_in[10];

    // 262144 pixels / 4 per thread / 128 threads = 512 blocks, one kernel.
    attn_fused_kernel<<<512, 128>>>(
        (const ulonglong2*)Z, (ulonglong2*)d_out,
        W_in, b_in, W_q, b_q, W_k, W_v, b_v, W_o, b_o);
}